// round 8
// baseline (speedup 1.0000x reference)
#include <cuda_runtime.h>

// Problem shape (fixed by the reference):
//   z: (16, 3, 256, 256) f32 ; out: (16, 3, 256, 256) f32
#define HID   64
#define ZCH   3
#define TD    512
#define NB    16
#define HWP   (256 * 256)          // pixels per (b, ch) plane
#define HW4   (HWP / 4)            // float4 groups per plane = 16384

// ---------------------------------------------------------------------------
// Constants, packed as float4.
//   g_cv[0] = (M00, M11, M22, 2*M01)
//   g_cv[1] = (2*M02, 2*M12, gamma, alpha)
//   g_cv[2] = (c, w0n, w1n, w2n)
//   g_cv[3] = (P00, P01, P02, r0)
//   g_cv[4] = (P10, P11, P12, r1)
//   g_cv[5] = (P20, P21, P22, r2)
//   g_cv[6] = (ob0, ob1, ob2, 0)
//   g_pb[b][0] = (d0, d1, d2, e)     d = 2 A^T u,  e = |u|^2,  u = zb - t(b)
//   g_pb[b][1] = (q0, q1, q2, s)     q = A^T t,    s = t . zb
// ---------------------------------------------------------------------------
__device__ float4 g_cv[7];
__device__ float4 g_pb[NB][2];
__device__ unsigned g_flag = 0;    // prep blocks completed
__device__ unsigned g_done = 0;    // blocks retired (launch-invariant reset)

__device__ __forceinline__ float wsum(float v) {
    #pragma unroll
    for (int o = 16; o; o >>= 1) v += __shfl_xor_sync(0xffffffffu, v, o);
    return v;
}

// ---------------------------------------------------------------------------
// Single fused kernel, 128-thread blocks, __launch_bounds__(128, 8):
// <= 64 regs/thread -> 8 CTAs/SM -> capacity 1184 CTAs >= grid 1040 -> ONE
// WAVE. Spin-wait is then safe: prep CTAs (bids 0..15) are co-resident with
// every consumer; consumers' z-loads are already in flight while they wait.
// ---------------------------------------------------------------------------
__global__ void __launch_bounds__(128, 8) fused_all_kernel(
    const float* __restrict__ z,    // (NB, 3, H, W)
    float*       __restrict__ out,
    const float* __restrict__ tv,   // (NB, TD)
    const float* __restrict__ A,    // (HID, 3) z_proj_w
    const float* __restrict__ zpb,  // (HID,)   z_proj_b
    const float* __restrict__ tw,   // (HID, TD)
    const float* __restrict__ tpb,  // (HID,)
    const float* __restrict__ W,    // (3, HID) out_w
    const float* __restrict__ ob,   // (3,)
    const float* __restrict__ lg,   // log_gamma
    const float* __restrict__ al,   // alpha
    const float* __restrict__ cp,   // c
    const float* __restrict__ wv)   // (3,)
{
    const int bid  = (int)blockIdx.x;
    const int tid  = (int)threadIdx.x;

    if (bid >= NB) {
        // ================= STREAMING (1024 blocks, 2 groups/thread) ========
        const int cid = bid - NB;
        const int b   = cid >> 6;                        // 64 blocks/batch
        const int pA  = ((cid & 63) << 8) + tid;         // group A
        const int pB  = pA + 128;                        // group B

        const float4* zb4 = (const float4*)(z   + (size_t)b * ZCH * HWP);
        float4*       ob4 = (float4*)      (out + (size_t)b * ZCH * HWP);

        // 6 independent front-batched loads — in flight while prep runs
        const float4 iA0 = zb4[pA];
        const float4 iA1 = zb4[pA + HW4];
        const float4 iA2 = zb4[pA + 2 * HW4];
        const float4 iB0 = zb4[pB];
        const float4 iB1 = zb4[pB + HW4];
        const float4 iB2 = zb4[pB + 2 * HW4];

        // wait for prep (acquire + block broadcast)
        if (tid == 0) {
            while (*(volatile unsigned*)&g_flag < NB) __nanosleep(64);
            __threadfence();
        }
        __syncthreads();

        const float4 c0 = g_cv[0], c1 = g_cv[1], c2 = g_cv[2];
        const float4 c3 = g_cv[3], c4 = g_cv[4], c5 = g_cv[5], c6 = g_cv[6];
        const float4 p0 = g_pb[b][0], p1 = g_pb[b][1];

        const float M00 = c0.x, M11 = c0.y, M22 = c0.z, M01 = c0.w;
        const float M02 = c1.x, M12 = c1.y, ngam = -c1.z, alpha = c1.w;
        const float cc = c2.x, w0n = c2.y, w1n = c2.z, w2n = c2.w;
        const float d0 = p0.x, d1 = p0.y, d2 = p0.z, e = p0.w;
        const float q0 = p1.x, q1 = p1.y, q2 = p1.z, s = p1.w;

        auto pixel = [&](float x, float y, float zz, float& o0, float& o1, float& o2) {
            float dist = e;
            dist = fmaf(fmaf(M00, x, fmaf(M01, y, fmaf(M02, zz, d0))), x, dist);
            dist = fmaf(fmaf(M11, y, fmaf(M12, zz, d1)),               y, dist);
            dist = fmaf(fmaf(M22, zz, d2),                             zz, dist);

            float klin = fmaf(q0, x, fmaf(q1, y, fmaf(q2, zz, s)));
            float krbf = __expf(ngam * dist);
            float t1   = fmaf(alpha, klin, cc);
            float k    = fmaf(w0n, krbf, fmaf(w1n, klin, w2n * (t1 * t1)));
            float scale = 1.f + 1.f / (1.f + __expf(-k));   // 1 + sigmoid(k)

            o0 = fmaf(scale, fmaf(c3.x, x, fmaf(c3.y, y, fmaf(c3.z, zz, c3.w))), c6.x);
            o1 = fmaf(scale, fmaf(c4.x, x, fmaf(c4.y, y, fmaf(c4.z, zz, c4.w))), c6.y);
            o2 = fmaf(scale, fmaf(c5.x, x, fmaf(c5.y, y, fmaf(c5.z, zz, c5.w))), c6.z);
        };

        float o0[4], o1[4], o2[4];
        {
            const float a0[4] = { iA0.x, iA0.y, iA0.z, iA0.w };
            const float a1[4] = { iA1.x, iA1.y, iA1.z, iA1.w };
            const float a2[4] = { iA2.x, iA2.y, iA2.z, iA2.w };
            #pragma unroll
            for (int i = 0; i < 4; i++) pixel(a0[i], a1[i], a2[i], o0[i], o1[i], o2[i]);
            ob4[pA]           = make_float4(o0[0], o0[1], o0[2], o0[3]);
            ob4[pA + HW4]     = make_float4(o1[0], o1[1], o1[2], o1[3]);
            ob4[pA + 2 * HW4] = make_float4(o2[0], o2[1], o2[2], o2[3]);
        }
        {
            const float a0[4] = { iB0.x, iB0.y, iB0.z, iB0.w };
            const float a1[4] = { iB1.x, iB1.y, iB1.z, iB1.w };
            const float a2[4] = { iB2.x, iB2.y, iB2.z, iB2.w };
            #pragma unroll
            for (int i = 0; i < 4; i++) pixel(a0[i], a1[i], a2[i], o0[i], o1[i], o2[i]);
            ob4[pB]           = make_float4(o0[0], o0[1], o0[2], o0[3]);
            ob4[pB + HW4]     = make_float4(o1[0], o1[1], o1[2], o1[3]);
            ob4[pB + 2 * HW4] = make_float4(o2[0], o2[1], o2[2], o2[3]);
        }
    } else {
        // ================= PREP (batch b = bid; 4 warps) ===================
        __shared__ float4 tv_sh[TD / 4];
        __shared__ float t_sh[HID], u_sh[HID], zpb_sh[HID];
        __shared__ float A_sh[HID * 3], W_sh[3 * HID];

        const int b    = bid;
        const int wid  = tid >> 5;
        const int lane = tid & 31;

        if (tid < TD / 4) tv_sh[tid] = ((const float4*)(tv + b * TD))[tid];
        #pragma unroll
        for (int i = tid; i < HID * 3; i += 128) A_sh[i] = A[i];
        #pragma unroll
        for (int i = tid; i < 3 * HID; i += 128) W_sh[i] = W[i];
        if (tid < HID) zpb_sh[tid] = zpb[tid];
        __syncthreads();

        // Coalesced GEMV: warp w owns outputs o = 16w .. 16w+15
        const float4* tw4 = (const float4*)tw;
        #pragma unroll
        for (int j = 0; j < 16; j++) {
            const int o = wid * 16 + j;
            float s = 0.f;
            #pragma unroll
            for (int k = 0; k < 4; k++) {
                const float4 a = tw4[o * (TD / 4) + k * 32 + lane];
                const float4 v = tv_sh[k * 32 + lane];
                s = fmaf(a.x, v.x, fmaf(a.y, v.y, fmaf(a.z, v.z, fmaf(a.w, v.w, s))));
            }
            s = wsum(s);
            if (lane == 0) {
                const float tval = s + tpb[o];
                t_sh[o] = tval;
                u_sh[o] = zpb_sh[o] - tval;   // u = zb - t
            }
        }
        __syncthreads();

        float* cf  = (float*)g_cv;
        float* pbf = (float*)g_pb;

        const float tl = t_sh[lane],   th = t_sh[lane + 32];
        const float ul = u_sh[lane],   uh = u_sh[lane + 32];
        const float zl = zpb_sh[lane], zh = zpb_sh[lane + 32];

        if (wid == 0) {
            #pragma unroll
            for (int i = 0; i < 3; i++) {
                const float a1 = A_sh[lane * 3 + i], a2 = A_sh[(lane + 32) * 3 + i];
                float d = wsum(a1 * ul + a2 * uh);
                float q = wsum(a1 * tl + a2 * th);
                if (lane == 0) { pbf[b * 8 + i] = 2.f * d; pbf[b * 8 + 4 + i] = q; }
            }
        } else if (wid == 1) {
            float e  = wsum(ul * ul + uh * uh);
            float s2 = wsum(tl * zl + th * zh);
            if (lane == 0) { pbf[b * 8 + 3] = e; pbf[b * 8 + 7] = s2; }
        }

        if (b == 0) {
            if (wid == 2) {
                // M (6 entries, off-diag pre-doubled) + r + scalars + ob
                const int ii[6] = {0, 1, 2, 0, 0, 1};
                const int jj[6] = {0, 1, 2, 1, 2, 2};
                #pragma unroll
                for (int k = 0; k < 6; k++) {
                    float m = wsum(A_sh[lane * 3 + ii[k]] * A_sh[lane * 3 + jj[k]]
                                 + A_sh[(lane + 32) * 3 + ii[k]] * A_sh[(lane + 32) * 3 + jj[k]]);
                    if (lane == 0) cf[k] = (k < 3) ? m : 2.f * m;
                }
                #pragma unroll
                for (int i = 0; i < 3; i++) {
                    float rr = wsum(W_sh[i * HID + lane] * zl + W_sh[i * HID + lane + 32] * zh);
                    if (lane == 0) cf[15 + 4 * i] = rr;
                }
                if (lane == 0) {
                    cf[6] = expf(lg[0]);
                    cf[7] = al[0];
                    cf[8] = cp[0];
                    float inv = 1.f / (wv[0] + wv[1] + wv[2] + 1e-8f);
                    cf[9]  = wv[0] * inv;
                    cf[10] = wv[1] * inv;
                    cf[11] = wv[2] * inv;
                }
                if (lane >= 1 && lane <= 3) cf[24 + lane - 1] = ob[lane - 1];
            } else if (wid == 3) {
                // P = W A
                #pragma unroll
                for (int i = 0; i < 3; i++)
                    #pragma unroll
                    for (int j = 0; j < 3; j++) {
                        float p = wsum(W_sh[i * HID + lane] * A_sh[lane * 3 + j]
                                     + W_sh[i * HID + lane + 32] * A_sh[(lane + 32) * 3 + j]);
                        if (lane == 0) cf[12 + 4 * i + j] = p;
                    }
            }
        }

        __syncthreads();                       // all prep writes issued
        if (tid == 0) {
            __threadfence();                   // release
            atomicAdd(&g_flag, 1u);
        }
    }

    // ---- launch-invariant counter reset (last block to retire) ----
    if (tid == 0) {
        const unsigned old = atomicAdd(&g_done, 1u);
        if (old == gridDim.x - 1u) {
            atomicExch(&g_done, 0u);
            atomicExch(&g_flag, 0u);
        }
    }
}

// ---------------------------------------------------------------------------
extern "C" void kernel_launch(void* const* d_in, const int* in_sizes, int n_in,
                              void* d_out, int out_size)
{
    const float* z    = (const float*)d_in[0];
    const float* tv   = (const float*)d_in[1];
    const float* zpw  = (const float*)d_in[2];
    const float* zpb  = (const float*)d_in[3];
    const float* tw   = (const float*)d_in[4];
    const float* tpb  = (const float*)d_in[5];
    const float* ow   = (const float*)d_in[6];
    const float* ob   = (const float*)d_in[7];
    const float* lg   = (const float*)d_in[8];
    const float* al   = (const float*)d_in[9];
    const float* cp   = (const float*)d_in[10];
    const float* wv   = (const float*)d_in[11];
    float* out = (float*)d_out;

    const int B = in_sizes[0] / (ZCH * HWP);      // 16

    // 16 prep blocks + 1024 streaming blocks, 128 threads each -> one wave
    fused_all_kernel<<<NB + (B * HW4) / 256, 128>>>(
        z, out, tv, zpw, zpb, tw, tpb, ow, ob, lg, al, cp, wv);
}

// round 9
// speedup vs baseline: 1.1241x; 1.1241x over previous
#include <cuda_runtime.h>

// Problem shape (fixed by the reference):
//   z: (16, 3, 256, 256) f32 ; out: (16, 3, 256, 256) f32
#define HID   64
#define ZCH   3
#define TD    512
#define NB    16
#define HWP   (256 * 256)          // pixels per (b, ch) plane
#define HW4   (HWP / 4)            // float4 groups per plane = 16384
#define NTRIP (NB * HW4)           // total float4-triples = 262144

// ---------------------------------------------------------------------------
// Constants, packed as float4.
//   g_cv[0] = (M00, M11, M22, 2*M01)
//   g_cv[1] = (2*M02, 2*M12, gamma, alpha)
//   g_cv[2] = (c, w0n, w1n, w2n)
//   g_cv[3] = (P00, P01, P02, r0)
//   g_cv[4] = (P10, P11, P12, r1)
//   g_cv[5] = (P20, P21, P22, r2)
//   g_cv[6] = (ob0, ob1, ob2, 0)
//   g_pb[b][0] = (d0, d1, d2, e)     d = 2 A^T u,  e = |u|^2,  u = zb - t(b)
//   g_pb[b][1] = (q0, q1, q2, s)     q = A^T t,    s = t . zb
// ---------------------------------------------------------------------------
__device__ float4 g_cv[7];
__device__ float4 g_pb[NB][2];

__device__ __forceinline__ float wsum(float v) {
    #pragma unroll
    for (int o = 16; o; o >>= 1) v += __shfl_xor_sync(0xffffffffu, v, o);
    return v;
}

// ---------------------------------------------------------------------------
// Prep: one block per batch, 256 threads (8 warps). Warp w owns outputs
// o = 8w..8w+7; the output loop is FULLY UNROLLED so the compiler can
// front-batch all 32 independent LDG.128s per lane instead of exposing
// 16 serial dependent latency rounds (the R3 prep's bottleneck).
// ---------------------------------------------------------------------------
__global__ void __launch_bounds__(256) prep_kernel(
    const float* __restrict__ tv,   // (NB, TD)
    const float* __restrict__ A,    // (HID, 3) z_proj_w
    const float* __restrict__ zpb,  // (HID,)   z_proj_b
    const float* __restrict__ tw,   // (HID, TD)
    const float* __restrict__ tpb,  // (HID,)
    const float* __restrict__ W,    // (3, HID) out_w
    const float* __restrict__ ob,   // (3,)
    const float* __restrict__ lg,   // log_gamma
    const float* __restrict__ al,   // alpha
    const float* __restrict__ cp,   // c
    const float* __restrict__ wv)   // (3,)
{
    __shared__ float4 tv_sh[TD / 4];
    __shared__ float t_sh[HID], u_sh[HID], zpb_sh[HID];
    __shared__ float A_sh[HID * 3], W_sh[3 * HID];

    const int b    = blockIdx.x;
    const int tid  = threadIdx.x;
    const int wid  = tid >> 5;
    const int lane = tid & 31;

    if (tid < TD / 4)   tv_sh[tid]  = ((const float4*)(tv + b * TD))[tid];
    if (tid < HID * 3)  A_sh[tid]   = A[tid];
    if (tid < 3 * HID)  W_sh[tid]   = W[tid];
    if (tid < HID)      zpb_sh[tid] = zpb[tid];
    __syncthreads();

    // GEMV: warp w owns 8 outputs; 8 independent accumulators; loads
    // across outputs are independent -> deep MLP after unrolling.
    {
        const float4* tw4 = (const float4*)tw;
        float acc[8];
        #pragma unroll
        for (int j = 0; j < 8; j++) acc[j] = 0.f;
        #pragma unroll
        for (int k = 0; k < 4; k++) {
            const float4 v = tv_sh[k * 32 + lane];
            #pragma unroll
            for (int j = 0; j < 8; j++) {
                const int o = wid * 8 + j;
                const float4 a = tw4[o * (TD / 4) + k * 32 + lane];
                acc[j] = fmaf(a.x, v.x, fmaf(a.y, v.y, fmaf(a.z, v.z, fmaf(a.w, v.w, acc[j]))));
            }
        }
        #pragma unroll
        for (int j = 0; j < 8; j++) {
            const float s = wsum(acc[j]);
            const int o = wid * 8 + j;
            if (lane == 0) {
                const float tval = s + tpb[o];
                t_sh[o] = tval;
                u_sh[o] = zpb_sh[o] - tval;   // u = zb - t
            }
        }
    }
    __syncthreads();

    float* cf  = (float*)g_cv;
    float* pbf = (float*)g_pb;

    const float tl = t_sh[lane],   th = t_sh[lane + 32];
    const float ul = u_sh[lane],   uh = u_sh[lane + 32];
    const float zl = zpb_sh[lane], zh = zpb_sh[lane + 32];

    if (wid == 0) {
        #pragma unroll
        for (int i = 0; i < 3; i++) {
            const float a1 = A_sh[lane * 3 + i], a2 = A_sh[(lane + 32) * 3 + i];
            float d = wsum(a1 * ul + a2 * uh);
            float q = wsum(a1 * tl + a2 * th);
            if (lane == 0) { pbf[b * 8 + i] = 2.f * d; pbf[b * 8 + 4 + i] = q; }
        }
    } else if (wid == 1) {
        float e  = wsum(ul * ul + uh * uh);
        float s2 = wsum(tl * zl + th * zh);
        if (lane == 0) { pbf[b * 8 + 3] = e; pbf[b * 8 + 7] = s2; }
    }

    if (b == 0) {
        if (wid == 2) {
            const int ii[6] = {0, 1, 2, 0, 0, 1};
            const int jj[6] = {0, 1, 2, 1, 2, 2};
            #pragma unroll
            for (int k = 0; k < 6; k++) {
                float m = wsum(A_sh[lane * 3 + ii[k]] * A_sh[lane * 3 + jj[k]]
                             + A_sh[(lane + 32) * 3 + ii[k]] * A_sh[(lane + 32) * 3 + jj[k]]);
                if (lane == 0) cf[k] = (k < 3) ? m : 2.f * m;
            }
        } else if (wid == 3) {
            #pragma unroll
            for (int i = 0; i < 3; i++)
                #pragma unroll
                for (int j = 0; j < 3; j++) {
                    float p = wsum(W_sh[i * HID + lane] * A_sh[lane * 3 + j]
                                 + W_sh[i * HID + lane + 32] * A_sh[(lane + 32) * 3 + j]);
                    if (lane == 0) cf[12 + 4 * i + j] = p;
                }
        } else if (wid == 4) {
            #pragma unroll
            for (int i = 0; i < 3; i++) {
                float rr = wsum(W_sh[i * HID + lane] * zl + W_sh[i * HID + lane + 32] * zh);
                if (lane == 0) cf[15 + 4 * i] = rr;
            }
            if (lane == 0) {
                cf[6] = expf(lg[0]);
                cf[7] = al[0];
                cf[8] = cp[0];
                float inv = 1.f / (wv[0] + wv[1] + wv[2] + 1e-8f);
                cf[9]  = wv[0] * inv;
                cf[10] = wv[1] * inv;
                cf[11] = wv[2] * inv;
            }
            if (lane >= 1 && lane <= 3) cf[24 + lane - 1] = ob[lane - 1];
        }
    }
}

// ---------------------------------------------------------------------------
// Main: PERSISTENT + SOFTWARE-PIPELINED. 296 CTAs (exactly 2/SM) x 256
// threads, grid-stride over 262144 float4-triples (~3.5 iters/thread).
// Each iteration prefetches the NEXT triple's 3 loads before computing the
// current one, so memory latency hides behind compute instead of being
// exposed once per CTA generation (the 8.2us floor of the one-shot shape).
// ---------------------------------------------------------------------------
#define MAIN_CTAS 296

__global__ void __launch_bounds__(256, 2) fused_main_kernel(
    const float* __restrict__ z, float* __restrict__ out)
{
    const int stride = MAIN_CTAS * 256;                 // 75776
    int g = (int)(blockIdx.x * 256 + threadIdx.x);

    // global constants once (broadcast, stay in registers)
    const float4 c0 = g_cv[0], c1 = g_cv[1], c2 = g_cv[2];
    const float4 c3 = g_cv[3], c4 = g_cv[4], c5 = g_cv[5], c6 = g_cv[6];

    const float M00 = c0.x, M11 = c0.y, M22 = c0.z, M01 = c0.w;
    const float M02 = c1.x, M12 = c1.y, ngam = -c1.z, alpha = c1.w;
    const float cc = c2.x, w0n = c2.y, w1n = c2.z, w2n = c2.w;

    // prologue: load triple for g
    int b  = g >> 14;
    int p4 = g & (HW4 - 1);
    const float4* zp = (const float4*)(z + (size_t)b * ZCH * HWP);
    float4 v0 = zp[p4], v1 = zp[p4 + HW4], v2 = zp[p4 + 2 * HW4];

    while (true) {
        // ---- prefetch next triple ----
        const int gn  = g + stride;
        const bool has = (gn < NTRIP);
        int bn = 0, p4n = 0;
        float4 n0, n1, n2;
        if (has) {
            bn  = gn >> 14;
            p4n = gn & (HW4 - 1);
            const float4* znp = (const float4*)(z + (size_t)bn * ZCH * HWP);
            n0 = znp[p4n];
            n1 = znp[p4n + HW4];
            n2 = znp[p4n + 2 * HW4];
        }

        // ---- per-batch constants (L1-resident broadcast) ----
        const float4 p0 = g_pb[b][0], p1 = g_pb[b][1];
        const float d0 = p0.x, d1 = p0.y, d2 = p0.z, e = p0.w;
        const float q0 = p1.x, q1 = p1.y, q2 = p1.z, s = p1.w;

        // ---- compute current triple (4 pixels) ----
        const float a0[4] = { v0.x, v0.y, v0.z, v0.w };
        const float a1[4] = { v1.x, v1.y, v1.z, v1.w };
        const float a2[4] = { v2.x, v2.y, v2.z, v2.w };
        float o0[4], o1[4], o2[4];

        #pragma unroll
        for (int i = 0; i < 4; i++) {
            const float x = a0[i], y = a1[i], zz = a2[i];

            float dist = e;
            dist = fmaf(fmaf(M00, x, fmaf(M01, y, fmaf(M02, zz, d0))), x, dist);
            dist = fmaf(fmaf(M11, y, fmaf(M12, zz, d1)),               y, dist);
            dist = fmaf(fmaf(M22, zz, d2),                             zz, dist);

            float klin = fmaf(q0, x, fmaf(q1, y, fmaf(q2, zz, s)));
            float krbf = __expf(ngam * dist);
            float t1   = fmaf(alpha, klin, cc);
            float k    = fmaf(w0n, krbf, fmaf(w1n, klin, w2n * (t1 * t1)));
            float scale = 1.f + 1.f / (1.f + __expf(-k));   // 1 + sigmoid(k)

            o0[i] = fmaf(scale, fmaf(c3.x, x, fmaf(c3.y, y, fmaf(c3.z, zz, c3.w))), c6.x);
            o1[i] = fmaf(scale, fmaf(c4.x, x, fmaf(c4.y, y, fmaf(c4.z, zz, c4.w))), c6.y);
            o2[i] = fmaf(scale, fmaf(c5.x, x, fmaf(c5.y, y, fmaf(c5.z, zz, c5.w))), c6.z);
        }

        float4* ob4 = (float4*)(out + (size_t)b * ZCH * HWP);
        ob4[p4]           = make_float4(o0[0], o0[1], o0[2], o0[3]);
        ob4[p4 + HW4]     = make_float4(o1[0], o1[1], o1[2], o1[3]);
        ob4[p4 + 2 * HW4] = make_float4(o2[0], o2[1], o2[2], o2[3]);

        if (!has) break;
        g = gn; b = bn; p4 = p4n;
        v0 = n0; v1 = n1; v2 = n2;
    }
}

// ---------------------------------------------------------------------------
extern "C" void kernel_launch(void* const* d_in, const int* in_sizes, int n_in,
                              void* d_out, int out_size)
{
    const float* z    = (const float*)d_in[0];
    const float* tv   = (const float*)d_in[1];
    const float* zpw  = (const float*)d_in[2];
    const float* zpb  = (const float*)d_in[3];
    const float* tw   = (const float*)d_in[4];
    const float* tpb  = (const float*)d_in[5];
    const float* ow   = (const float*)d_in[6];
    const float* ob   = (const float*)d_in[7];
    const float* lg   = (const float*)d_in[8];
    const float* al   = (const float*)d_in[9];
    const float* cp   = (const float*)d_in[10];
    const float* wv   = (const float*)d_in[11];
    float* out = (float*)d_out;

    const int B = in_sizes[0] / (ZCH * HWP);      // 16 (shape fixed)
    (void)B;

    prep_kernel<<<NB, 256>>>(tv, zpw, zpb, tw, tpb, ow, ob, lg, al, cp, wv);
    fused_main_kernel<<<MAIN_CTAS, 256>>>(z, out);
}

// round 10
// speedup vs baseline: 1.1805x; 1.0501x over previous
#include <cuda_runtime.h>

// Problem shape (fixed by the reference):
//   z: (16, 3, 256, 256) f32 ; out: (16, 3, 256, 256) f32
#define HID   64
#define ZCH   3
#define TD    512
#define NB    16
#define HWP   (256 * 256)          // pixels per (b, ch) plane
#define HW4   (HWP / 4)            // float4 groups per plane = 16384

// ---------------------------------------------------------------------------
// Constants, packed as float4.
//   g_cv[0] = (M00, M11, M22, 2*M01)
//   g_cv[1] = (2*M02, 2*M12, gamma, alpha)
//   g_cv[2] = (c, w0n, w1n, w2n)
//   g_cv[3] = (P00, P01, P02, r0)
//   g_cv[4] = (P10, P11, P12, r1)
//   g_cv[5] = (P20, P21, P22, r2)
//   g_cv[6] = (ob0, ob1, ob2, 0)
//   g_pb[b][0] = (d0, d1, d2, e)     d = 2 A^T u,  e = |u|^2,  u = zb - t(b)
//   g_pb[b][1] = (q0, q1, q2, s)     q = A^T t,    s = t . zb
// ---------------------------------------------------------------------------
__device__ float4 g_cv[7];
__device__ float4 g_pb[NB][2];

__device__ __forceinline__ float wsum(float v) {
    #pragma unroll
    for (int o = 16; o; o >>= 1) v += __shfl_xor_sync(0xffffffffu, v, o);
    return v;
}

// ---------------------------------------------------------------------------
// Prep: one block per batch, 256 threads (8 warps). Warp w owns outputs
// o = 8w..8w+7; output loop fully unrolled -> 32 independent LDG.128 per
// lane front-batched (deep MLP) instead of serial dependent rounds.
// ---------------------------------------------------------------------------
__global__ void __launch_bounds__(256) prep_kernel(
    const float* __restrict__ tv,   // (NB, TD)
    const float* __restrict__ A,    // (HID, 3) z_proj_w
    const float* __restrict__ zpb,  // (HID,)   z_proj_b
    const float* __restrict__ tw,   // (HID, TD)
    const float* __restrict__ tpb,  // (HID,)
    const float* __restrict__ W,    // (3, HID) out_w
    const float* __restrict__ ob,   // (3,)
    const float* __restrict__ lg,   // log_gamma
    const float* __restrict__ al,   // alpha
    const float* __restrict__ cp,   // c
    const float* __restrict__ wv)   // (3,)
{
    __shared__ float4 tv_sh[TD / 4];
    __shared__ float t_sh[HID], u_sh[HID], zpb_sh[HID];
    __shared__ float A_sh[HID * 3], W_sh[3 * HID];

    const int b    = blockIdx.x;
    const int tid  = threadIdx.x;
    const int wid  = tid >> 5;
    const int lane = tid & 31;

    if (tid < TD / 4)   tv_sh[tid]  = ((const float4*)(tv + b * TD))[tid];
    if (tid < HID * 3)  A_sh[tid]   = A[tid];
    if (tid < 3 * HID)  W_sh[tid]   = W[tid];
    if (tid < HID)      zpb_sh[tid] = zpb[tid];
    __syncthreads();

    // GEMV: warp w owns 8 outputs; 8 independent accumulators.
    {
        const float4* tw4 = (const float4*)tw;
        float acc[8];
        #pragma unroll
        for (int j = 0; j < 8; j++) acc[j] = 0.f;
        #pragma unroll
        for (int k = 0; k < 4; k++) {
            const float4 v = tv_sh[k * 32 + lane];
            #pragma unroll
            for (int j = 0; j < 8; j++) {
                const int o = wid * 8 + j;
                const float4 a = tw4[o * (TD / 4) + k * 32 + lane];
                acc[j] = fmaf(a.x, v.x, fmaf(a.y, v.y, fmaf(a.z, v.z, fmaf(a.w, v.w, acc[j]))));
            }
        }
        #pragma unroll
        for (int j = 0; j < 8; j++) {
            const float s = wsum(acc[j]);
            const int o = wid * 8 + j;
            if (lane == 0) {
                const float tval = s + tpb[o];
                t_sh[o] = tval;
                u_sh[o] = zpb_sh[o] - tval;   // u = zb - t
            }
        }
    }
    __syncthreads();

    float* cf  = (float*)g_cv;
    float* pbf = (float*)g_pb;

    const float tl = t_sh[lane],   th = t_sh[lane + 32];
    const float ul = u_sh[lane],   uh = u_sh[lane + 32];
    const float zl = zpb_sh[lane], zh = zpb_sh[lane + 32];

    if (wid == 0) {
        #pragma unroll
        for (int i = 0; i < 3; i++) {
            const float a1 = A_sh[lane * 3 + i], a2 = A_sh[(lane + 32) * 3 + i];
            float d = wsum(a1 * ul + a2 * uh);
            float q = wsum(a1 * tl + a2 * th);
            if (lane == 0) { pbf[b * 8 + i] = 2.f * d; pbf[b * 8 + 4 + i] = q; }
        }
    } else if (wid == 1) {
        float e  = wsum(ul * ul + uh * uh);
        float s2 = wsum(tl * zl + th * zh);
        if (lane == 0) { pbf[b * 8 + 3] = e; pbf[b * 8 + 7] = s2; }
    }

    if (b == 0) {
        if (wid == 2) {
            const int ii[6] = {0, 1, 2, 0, 0, 1};
            const int jj[6] = {0, 1, 2, 1, 2, 2};
            #pragma unroll
            for (int k = 0; k < 6; k++) {
                float m = wsum(A_sh[lane * 3 + ii[k]] * A_sh[lane * 3 + jj[k]]
                             + A_sh[(lane + 32) * 3 + ii[k]] * A_sh[(lane + 32) * 3 + jj[k]]);
                if (lane == 0) cf[k] = (k < 3) ? m : 2.f * m;
            }
        } else if (wid == 3) {
            #pragma unroll
            for (int i = 0; i < 3; i++)
                #pragma unroll
                for (int j = 0; j < 3; j++) {
                    float p = wsum(W_sh[i * HID + lane] * A_sh[lane * 3 + j]
                                 + W_sh[i * HID + lane + 32] * A_sh[(lane + 32) * 3 + j]);
                    if (lane == 0) cf[12 + 4 * i + j] = p;
                }
        } else if (wid == 4) {
            #pragma unroll
            for (int i = 0; i < 3; i++) {
                float rr = wsum(W_sh[i * HID + lane] * zl + W_sh[i * HID + lane + 32] * zh);
                if (lane == 0) cf[15 + 4 * i] = rr;
            }
            if (lane == 0) {
                cf[6] = expf(lg[0]);
                cf[7] = al[0];
                cf[8] = cp[0];
                float inv = 1.f / (wv[0] + wv[1] + wv[2] + 1e-8f);
                cf[9]  = wv[0] * inv;
                cf[10] = wv[1] * inv;
                cf[11] = wv[2] * inv;
            }
            if (lane >= 1 && lane <= 3) cf[24 + lane - 1] = ob[lane - 1];
        }
    }
}

// ---------------------------------------------------------------------------
// Main: R3's measured-best shape (1024 blocks x 256 threads, one float4
// triple per thread) with a shortened compute body:
//   1 + sigmoid(k) = (2 + E) / (1 + E),  E = exp(-k)   via __fdividef
// (single MUFU.RCP instead of the full-precision Newton division chain).
// ---------------------------------------------------------------------------
__global__ void __launch_bounds__(256) fused_main_kernel(
    const float* __restrict__ z, float* __restrict__ out)
{
    const unsigned g  = blockIdx.x * 256u + threadIdx.x;
    const int b  = (int)(g >> 14);        // / HW4
    const int p4 = (int)(g & (HW4 - 1));

    const float4* zb4 = (const float4*)(z   + (size_t)b * ZCH * HWP);
    float4*       ob4 = (float4*)      (out + (size_t)b * ZCH * HWP);

    // front-batched data loads (MLP=3)
    const float4 v0 = zb4[p4];
    const float4 v1 = zb4[p4 + HW4];
    const float4 v2 = zb4[p4 + 2 * HW4];

    // vectorized constant loads (9 x LDG.128, broadcast)
    const float4 c0 = g_cv[0], c1 = g_cv[1], c2 = g_cv[2];
    const float4 c3 = g_cv[3], c4 = g_cv[4], c5 = g_cv[5], c6 = g_cv[6];
    const float4 p0 = g_pb[b][0], p1 = g_pb[b][1];

    const float M00 = c0.x, M11 = c0.y, M22 = c0.z, M01 = c0.w;
    const float M02 = c1.x, M12 = c1.y, ngam = -c1.z, alpha = c1.w;
    const float cc = c2.x, w0n = c2.y, w1n = c2.z, w2n = c2.w;
    const float d0 = p0.x, d1 = p0.y, d2 = p0.z, e = p0.w;
    const float q0 = p1.x, q1 = p1.y, q2 = p1.z, s = p1.w;

    const float a0[4] = { v0.x, v0.y, v0.z, v0.w };
    const float a1[4] = { v1.x, v1.y, v1.z, v1.w };
    const float a2[4] = { v2.x, v2.y, v2.z, v2.w };
    float o0[4], o1[4], o2[4];

    #pragma unroll
    for (int i = 0; i < 4; i++) {
        const float x = a0[i], y = a1[i], zz = a2[i];

        // dist = z'Mz + d.z + e
        float dist = e;
        dist = fmaf(fmaf(M00, x, fmaf(M01, y, fmaf(M02, zz, d0))), x, dist);
        dist = fmaf(fmaf(M11, y, fmaf(M12, zz, d1)),               y, dist);
        dist = fmaf(fmaf(M22, zz, d2),                             zz, dist);

        // k_lin = q.z + s
        float klin = fmaf(q0, x, fmaf(q1, y, fmaf(q2, zz, s)));

        float krbf = __expf(ngam * dist);
        float t1   = fmaf(alpha, klin, cc);
        float k    = fmaf(w0n, krbf, fmaf(w1n, klin, w2n * (t1 * t1)));

        // scale = 1 + sigmoid(k) = (2 + E) / (1 + E), E = exp(-k)
        const float E = __expf(-k);
        const float scale = __fdividef(2.f + E, 1.f + E);

        o0[i] = fmaf(scale, fmaf(c3.x, x, fmaf(c3.y, y, fmaf(c3.z, zz, c3.w))), c6.x);
        o1[i] = fmaf(scale, fmaf(c4.x, x, fmaf(c4.y, y, fmaf(c4.z, zz, c4.w))), c6.y);
        o2[i] = fmaf(scale, fmaf(c5.x, x, fmaf(c5.y, y, fmaf(c5.z, zz, c5.w))), c6.z);
    }

    ob4[p4]           = make_float4(o0[0], o0[1], o0[2], o0[3]);
    ob4[p4 + HW4]     = make_float4(o1[0], o1[1], o1[2], o1[3]);
    ob4[p4 + 2 * HW4] = make_float4(o2[0], o2[1], o2[2], o2[3]);
}

// ---------------------------------------------------------------------------
extern "C" void kernel_launch(void* const* d_in, const int* in_sizes, int n_in,
                              void* d_out, int out_size)
{
    const float* z    = (const float*)d_in[0];
    const float* tv   = (const float*)d_in[1];
    const float* zpw  = (const float*)d_in[2];
    const float* zpb  = (const float*)d_in[3];
    const float* tw   = (const float*)d_in[4];
    const float* tpb  = (const float*)d_in[5];
    const float* ow   = (const float*)d_in[6];
    const float* ob   = (const float*)d_in[7];
    const float* lg   = (const float*)d_in[8];
    const float* al   = (const float*)d_in[9];
    const float* cp   = (const float*)d_in[10];
    const float* wv   = (const float*)d_in[11];
    float* out = (float*)d_out;

    const int B = in_sizes[0] / (ZCH * HWP);      // 16

    prep_kernel<<<NB, 256>>>(tv, zpw, zpb, tw, tpb, ow, ob, lg, al, cp, wv);
    fused_main_kernel<<<(B * HW4) / 256, 256>>>(z, out);
}